// round 5
// baseline (speedup 1.0000x reference)
#include <cuda_runtime.h>
#include <math.h>

// FactorPredictor: N=200000 stocks, D=512, H=256, K=64 heads.
// Pipeline: prep (qWk, q.bk) -> score GEMM + exp + partial sums
//           -> pooled GEMM (split-N partials) -> reduce -> head projection.
// All fp32; inner GEMMs use packed fma.rn.f32x2 (sm_100+) for 2x FFMA rate.

#define NN 200000
#define DD 512
#define HH 256
#define KK 64
#define SCALE 0.0625f        // 1/sqrt(256)
#define NT 782               // ceil(NN/256)
#define SGRID 296
#define NSLICE 37
#define SLICE 5408           // 37*5408 >= NN, multiple of 32

// ---- scratch (no allocations allowed) ----
__device__ __align__(256) float g_qWkT[DD * KK];                  // [d][k]
__device__ __align__(256) float g_qbk[KK];
__device__ __align__(256) float g_sumpart[SGRID * KK];
__device__ __align__(256) float g_P[(size_t)NN * KK];             // exp(score), [n][k]
__device__ __align__(256) float g_part[148 * KK * 128];
__device__ __align__(256) float g_pooled[KK * DD];

// ---- f32x2 helpers ----
__device__ __forceinline__ void fma2(unsigned long long &c, unsigned long long a,
                                     unsigned long long b) {
    asm("fma.rn.f32x2 %0, %1, %2, %0;" : "+l"(c) : "l"(a), "l"(b));
}
__device__ __forceinline__ unsigned long long pk2(float lo, float hi) {
    unsigned long long r;
    asm("mov.b64 %0, {%1, %2};" : "=l"(r) : "f"(lo), "f"(hi));
    return r;
}
__device__ __forceinline__ float2 upk2(unsigned long long v) {
    float2 r;
    asm("mov.b64 {%0, %1}, %2;" : "=f"(r.x), "=f"(r.y) : "l"(v));
    return r;
}

// ---- K0: qWkT[d][k] = sum_h q[k,h]*Wk[k,h,d]; qbk[k] = q[k,:].bk[k,:] ----
__global__ __launch_bounds__(512) void prep_kernel(const float* __restrict__ q,
                                                   const float* __restrict__ Wk,
                                                   const float* __restrict__ bk) {
    const int k = blockIdx.x, t = threadIdx.x;
    __shared__ float qs[HH];
    __shared__ float red[256];
    if (t < HH) qs[t] = q[k * HH + t];
    __syncthreads();
    const float* w = Wk + (size_t)k * HH * DD + t;
    float acc = 0.f;
#pragma unroll 8
    for (int h = 0; h < HH; h++) acc += qs[h] * w[(size_t)h * DD];
    g_qWkT[t * KK + k] = acc;
    if (t < HH) red[t] = qs[t] * bk[k * HH + t];
    __syncthreads();
    for (int o = 128; o > 0; o >>= 1) {
        if (t < o) red[t] += red[t + o];
        __syncthreads();
    }
    if (t == 0) g_qbk[k] = red[0];
}

// ---- K1: scores = qWk @ e^T; P = exp((s+qbk)*SCALE); per-block k-sums ----
// Tile 64k x 256n per iteration, d-chunks of 32. 256 thr, thread tile 8k x 8n.
__global__ __launch_bounds__(256, 2) void score_kernel(const float* __restrict__ e) {
    __shared__ float As[32 * 64];
    __shared__ float Bs[32 * 260];
    const int t = threadIdx.x, tx = t & 31, ty = t >> 5;
    float qb[8];
#pragma unroll
    for (int kk = 0; kk < 8; kk++) qb[kk] = g_qbk[ty * 8 + kk];
    float sumacc[8] = {0.f, 0.f, 0.f, 0.f, 0.f, 0.f, 0.f, 0.f};

    for (int tile = blockIdx.x; tile < NT; tile += gridDim.x) {
        const int n0 = tile * 256;
        unsigned long long acc[8][4];
#pragma unroll
        for (int a = 0; a < 8; a++)
#pragma unroll
            for (int b = 0; b < 4; b++) acc[a][b] = 0ull;

        for (int d0 = 0; d0 < DD; d0 += 32) {
            __syncthreads();
#pragma unroll
            for (int j = 0; j < 8; j++)
                As[t + j * 256] = g_qWkT[d0 * 64 + t + j * 256];
#pragma unroll
            for (int j = 0; j < 8; j++) {
                int f = t + j * 256;
                int nn = f >> 3, fq = f & 7;
                int n = n0 + nn;
                float4 v = make_float4(0.f, 0.f, 0.f, 0.f);
                if (n < NN) v = *(const float4*)(e + (size_t)n * DD + d0 + fq * 4);
                Bs[(fq * 4 + 0) * 260 + nn] = v.x;
                Bs[(fq * 4 + 1) * 260 + nn] = v.y;
                Bs[(fq * 4 + 2) * 260 + nn] = v.z;
                Bs[(fq * 4 + 3) * 260 + nn] = v.w;
            }
            __syncthreads();
#pragma unroll
            for (int dc = 0; dc < 32; dc++) {
                float4 a0 = *(const float4*)(As + dc * 64 + ty * 8);
                float4 a1 = *(const float4*)(As + dc * 64 + ty * 8 + 4);
                float4 b0 = *(const float4*)(Bs + dc * 260 + tx * 4);
                float4 b1 = *(const float4*)(Bs + dc * 260 + 128 + tx * 4);
                unsigned long long bp0 = pk2(b0.x, b0.y), bp1 = pk2(b0.z, b0.w);
                unsigned long long bp2 = pk2(b1.x, b1.y), bp3 = pk2(b1.z, b1.w);
                float av[8] = {a0.x, a0.y, a0.z, a0.w, a1.x, a1.y, a1.z, a1.w};
#pragma unroll
                for (int kk = 0; kk < 8; kk++) {
                    unsigned long long ap = pk2(av[kk], av[kk]);
                    fma2(acc[kk][0], ap, bp0);
                    fma2(acc[kk][1], ap, bp1);
                    fma2(acc[kk][2], ap, bp2);
                    fma2(acc[kk][3], ap, bp3);
                }
            }
        }
        // epilogue: exp, store P (n-major), accumulate sums
        float pv[8][8];
#pragma unroll
        for (int kk = 0; kk < 8; kk++) {
            float2 v;
            v = upk2(acc[kk][0]); pv[0][kk] = v.x; pv[1][kk] = v.y;
            v = upk2(acc[kk][1]); pv[2][kk] = v.x; pv[3][kk] = v.y;
            v = upk2(acc[kk][2]); pv[4][kk] = v.x; pv[5][kk] = v.y;
            v = upk2(acc[kk][3]); pv[6][kk] = v.x; pv[7][kk] = v.y;
        }
#pragma unroll
        for (int j = 0; j < 8; j++) {
            int n = n0 + (j < 4 ? tx * 4 + j : 128 + tx * 4 + (j - 4));
            if (n < NN) {
#pragma unroll
                for (int kk = 0; kk < 8; kk++) {
                    float p = __expf((pv[j][kk] + qb[kk]) * SCALE);
                    pv[j][kk] = p;
                    sumacc[kk] += p;
                }
                *(float4*)(g_P + (size_t)n * 64 + ty * 8) =
                    make_float4(pv[j][0], pv[j][1], pv[j][2], pv[j][3]);
                *(float4*)(g_P + (size_t)n * 64 + ty * 8 + 4) =
                    make_float4(pv[j][4], pv[j][5], pv[j][6], pv[j][7]);
            }
        }
    }
#pragma unroll
    for (int kk = 0; kk < 8; kk++) {
        float s = sumacc[kk];
#pragma unroll
        for (int o = 16; o > 0; o >>= 1) s += __shfl_xor_sync(0xffffffffu, s, o);
        if (tx == 0) g_sumpart[blockIdx.x * 64 + ty * 8 + kk] = s;
    }
}

// ---- K2: partial pooled[k][d] = sum_{n in slice} P[n][k]*e[n][d] ----
// grid = 4 d-chunks x 37 n-slices. 256 thr, C tile 64k x 128d, thread 8k x 4d.
__global__ __launch_bounds__(256, 2) void pool_kernel(const float* __restrict__ e) {
    __shared__ float Ps[32 * 64];
    __shared__ float Es[32 * 128];
    const int t = threadIdx.x, tx = t & 31, ty = t >> 5;
    const int d0 = (blockIdx.x & 3) * 128;
    const int nbeg = (blockIdx.x >> 2) * SLICE;
    const int nend = (nbeg + SLICE < NN) ? nbeg + SLICE : NN;

    unsigned long long acc[8][2];
#pragma unroll
    for (int a = 0; a < 8; a++) { acc[a][0] = 0ull; acc[a][1] = 0ull; }

    for (int n0 = nbeg; n0 < nend; n0 += 32) {
        __syncthreads();
#pragma unroll
        for (int j = 0; j < 2; j++) {
            int f = t + j * 256;
            int nn = f >> 4, kq = f & 15;
            int n = n0 + nn;
            float4 v = make_float4(0.f, 0.f, 0.f, 0.f);
            if (n < NN) v = *(const float4*)(g_P + (size_t)n * 64 + kq * 4);
            *(float4*)(Ps + nn * 64 + kq * 4) = v;
        }
#pragma unroll
        for (int j = 0; j < 4; j++) {
            int f = t + j * 256;
            int nn = f >> 5, dq = f & 31;
            int n = n0 + nn;
            float4 v = make_float4(0.f, 0.f, 0.f, 0.f);
            if (n < NN) v = *(const float4*)(e + (size_t)n * DD + d0 + dq * 4);
            *(float4*)(Es + nn * 128 + dq * 4) = v;
        }
        __syncthreads();
#pragma unroll
        for (int nn = 0; nn < 32; nn++) {
            float4 a0 = *(const float4*)(Ps + nn * 64 + ty * 8);
            float4 a1 = *(const float4*)(Ps + nn * 64 + ty * 8 + 4);
            float4 b  = *(const float4*)(Es + nn * 128 + tx * 4);
            unsigned long long bp0 = pk2(b.x, b.y), bp1 = pk2(b.z, b.w);
            float av[8] = {a0.x, a0.y, a0.z, a0.w, a1.x, a1.y, a1.z, a1.w};
#pragma unroll
            for (int kk = 0; kk < 8; kk++) {
                unsigned long long ap = pk2(av[kk], av[kk]);
                fma2(acc[kk][0], ap, bp0);
                fma2(acc[kk][1], ap, bp1);
            }
        }
    }
    float* dst = g_part + (size_t)blockIdx.x * (64 * 128);
#pragma unroll
    for (int kk = 0; kk < 8; kk++) {
        float2 v0 = upk2(acc[kk][0]), v1 = upk2(acc[kk][1]);
        *(float4*)(dst + (ty * 8 + kk) * 128 + tx * 4) =
            make_float4(v0.x, v0.y, v1.x, v1.y);
    }
}

// ---- K3: reduce split-N partials (deterministic order) ----
__global__ __launch_bounds__(512) void pool_reduce_kernel() {
    const int k = blockIdx.x, d = threadIdx.x;
    const int dq = d >> 7, dd = d & 127;
    float s = 0.f;
    for (int bs = 0; bs < NSLICE; bs++)
        s += g_part[(size_t)(bs * 4 + dq) * (64 * 128) + k * 128 + dd];
    g_pooled[k * DD + d] = s;
}

// ---- K4: normalize, Wv projection, mu/sigma ----
__global__ __launch_bounds__(256) void final_kernel(const float* __restrict__ Wv,
                                                    const float* __restrict__ bv,
                                                    const float* __restrict__ mu_w,
                                                    const float* __restrict__ mu_b,
                                                    const float* __restrict__ sigma_w,
                                                    const float* __restrict__ sigma_b,
                                                    float* __restrict__ out) {
    const int k = blockIdx.x, t = threadIdx.x;
    __shared__ float red[256];
    __shared__ float ps[DD];
    float s = 0.f;
    for (int b = t; b < SGRID; b += 256) s += g_sumpart[b * 64 + k];
    red[t] = s;
    __syncthreads();
    for (int o = 128; o > 0; o >>= 1) {
        if (t < o) red[t] += red[t + o];
        __syncthreads();
    }
    float inv = 1.f / red[0];
    for (int d = t; d < DD; d += 256) ps[d] = g_pooled[k * DD + d] * inv;
    __syncthreads();
    const float* wr = Wv + (size_t)k * HH * DD + (size_t)t * DD;
    float acc = 0.f;
    for (int d = 0; d < DD; d += 4) {
        float4 w = *(const float4*)(wr + d);
        acc += ps[d] * w.x + ps[d + 1] * w.y + ps[d + 2] * w.z + ps[d + 3] * w.w;
    }
    float h = acc + bv[k * HH + t];
    float m = h * mu_w[t];
    float g = h * sigma_w[t];
    __syncthreads();
    red[t] = m;
    __syncthreads();
    for (int o = 128; o > 0; o >>= 1) {
        if (t < o) red[t] += red[t + o];
        __syncthreads();
    }
    float mu = red[0] + mu_b[0];
    __syncthreads();
    red[t] = g;
    __syncthreads();
    for (int o = 128; o > 0; o >>= 1) {
        if (t < o) red[t] += red[t + o];
        __syncthreads();
    }
    if (t == 0) {
        out[k] = mu;
        out[KK + k] = expf(red[0] + sigma_b[0]);
    }
}

extern "C" void kernel_launch(void* const* d_in, const int* in_sizes, int n_in,
                              void* d_out, int out_size) {
    const float* e       = (const float*)d_in[0];
    const float* q       = (const float*)d_in[1];
    const float* Wk      = (const float*)d_in[2];
    const float* bk      = (const float*)d_in[3];
    const float* Wv      = (const float*)d_in[4];
    const float* bv      = (const float*)d_in[5];
    const float* mu_w    = (const float*)d_in[6];
    const float* mu_b    = (const float*)d_in[7];
    const float* sigma_w = (const float*)d_in[8];
    const float* sigma_b = (const float*)d_in[9];
    float* out = (float*)d_out;

    prep_kernel<<<KK, 512>>>(q, Wk, bk);
    score_kernel<<<SGRID, 256>>>(e);
    pool_kernel<<<148, 256>>>(e);
    pool_reduce_kernel<<<KK, 512>>>();
    final_kernel<<<KK, 256>>>(Wv, bv, mu_w, mu_b, sigma_w, sigma_b, out);
}

// round 7
// speedup vs baseline: 1.0598x; 1.0598x over previous
#include <cuda_runtime.h>
#include <math.h>
#include <stdint.h>

// N=200000, D=512, H=256, K=64.
// prep -> score (mma.sync tf32) -> sums -> pool (f32x2) -> reduce -> final.
#define NN 200000
#define DD 512
#define KK 64
#define HH 256
#define SCALE 0.0625f
#define NTILE 1563
#define SGRID 200
#define NSLICE 37
#define SLICE 5408

__device__ __align__(256) float g_qWk[KK * DD];     // [k][d]
__device__ __align__(256) float g_qbk[KK];
__device__ __align__(256) float g_sumpart[SGRID * KK];
__device__ __align__(256) float g_P[(size_t)NN * KK];   // [n][k]
__device__ __align__(256) float g_part[148 * KK * 128];
__device__ __align__(256) float g_pooled[KK * DD];

// ---- f32x2 helpers (pool) ----
__device__ __forceinline__ void fma2(unsigned long long &c, unsigned long long a, unsigned long long b) {
    asm("fma.rn.f32x2 %0, %1, %2, %0;" : "+l"(c) : "l"(a), "l"(b));
}
__device__ __forceinline__ unsigned long long pk2(float lo, float hi) {
    unsigned long long r; asm("mov.b64 %0, {%1, %2};" : "=l"(r) : "f"(lo), "f"(hi)); return r;
}
__device__ __forceinline__ float2 upk2(unsigned long long v) {
    float2 r; asm("mov.b64 {%0, %1}, %2;" : "=f"(r.x), "=f"(r.y) : "l"(v)); return r;
}
// ---- tf32 mma (arch-portable HMMA path, sm_80+) ----
__device__ __forceinline__ void mma8(float* c, const uint32_t* a, const uint32_t* b) {
    asm volatile(
        "mma.sync.aligned.m16n8k8.row.col.f32.tf32.tf32.f32 "
        "{%0,%1,%2,%3}, {%4,%5,%6,%7}, {%8,%9}, {%0,%1,%2,%3};"
        : "+f"(c[0]), "+f"(c[1]), "+f"(c[2]), "+f"(c[3])
        : "r"(a[0]), "r"(a[1]), "r"(a[2]), "r"(a[3]), "r"(b[0]), "r"(b[1]));
}

// ---- K0: prep: g_qWk[k][d], g_qbk ----
__global__ __launch_bounds__(512) void prep_kernel(const float* __restrict__ q,
                                                   const float* __restrict__ Wk,
                                                   const float* __restrict__ bk) {
    const int k = blockIdx.x, t = threadIdx.x;
    __shared__ float qs[HH]; __shared__ float red[256];
    if (t < HH) qs[t] = q[k * HH + t];
    __syncthreads();
    const float* w = Wk + (size_t)k * HH * DD + t;
    float acc = 0.f;
#pragma unroll 8
    for (int h = 0; h < HH; h++) acc += qs[h] * w[(size_t)h * DD];
    g_qWk[k * DD + t] = acc;
    if (t < HH) red[t] = qs[t] * bk[k * HH + t];
    __syncthreads();
    for (int o = 128; o > 0; o >>= 1) { if (t < o) red[t] += red[t + o]; __syncthreads(); }
    if (t == 0) g_qbk[k] = red[0];
}

// ---- K1: score GEMM via mma.sync tf32 + exp epilogue ----
// smem floats: QWK [64][516] = 33024 | EB0/EB1 [32][136] = 4352 each
// CBUF [128][68] = 8704 aliases EB region.  Total 41728 floats = 166912 B.
#define QWK_S 516
#define EB_S 136
#define EB_OFF 33024
#define SC_SMEM 166912
__global__ __launch_bounds__(256, 1) void score_kernel(const float* __restrict__ e) {
    extern __shared__ float sm[];
    float* QWK = sm;
    float* EB0 = sm + EB_OFF;
    float* EB1 = sm + EB_OFF + 4352;
    float* CBUF = sm + EB_OFF;
    __shared__ float sbk[KK];
    const int t = threadIdx.x, w = t >> 5, lane = t & 31;
    const int lq = lane >> 2, lr = lane & 3;
    if (t < KK) sbk[t] = g_qbk[t] * SCALE;
    // stage qWk -> smem (padded)
#pragma unroll
    for (int j = 0; j < 32; j++) {
        int f = t + j * 256, k = f >> 7, c4 = (f & 127) * 4;
        *(float4*)(QWK + k * QWK_S + c4) = *(const float4*)(g_qWk + k * DD + c4);
    }
    __syncthreads();

    for (int tile = blockIdx.x; tile < NTILE; tile += 148) {
        const int n0 = tile * 128;
        float4 rr[4];
        // prologue: chunk 0
#pragma unroll
        for (int j = 0; j < 4; j++) {
            int idx = t + j * 256, n = idx & 127, qd = idx >> 7;
            int gn = n0 + n;
            rr[j] = (gn < NN) ? *(const float4*)(e + (size_t)gn * DD + qd * 4)
                              : make_float4(0.f, 0.f, 0.f, 0.f);
        }
#pragma unroll
        for (int j = 0; j < 4; j++) {
            int idx = t + j * 256, n = idx & 127, qd = idx >> 7;
            EB0[(qd * 4 + 0) * EB_S + n] = rr[j].x;
            EB0[(qd * 4 + 1) * EB_S + n] = rr[j].y;
            EB0[(qd * 4 + 2) * EB_S + n] = rr[j].z;
            EB0[(qd * 4 + 3) * EB_S + n] = rr[j].w;
        }
        __syncthreads();

        float acc[4][2][4];
#pragma unroll
        for (int mt = 0; mt < 4; mt++)
#pragma unroll
            for (int nt = 0; nt < 2; nt++)
#pragma unroll
                for (int i = 0; i < 4; i++) acc[mt][nt][i] = 0.f;

        for (int c = 0; c < 16; c++) {
            if (c < 15) {
#pragma unroll
                for (int j = 0; j < 4; j++) {
                    int idx = t + j * 256, n = idx & 127, qd = idx >> 7;
                    int gn = n0 + n;
                    rr[j] = (gn < NN)
                        ? *(const float4*)(e + (size_t)gn * DD + (c + 1) * 32 + qd * 4)
                        : make_float4(0.f, 0.f, 0.f, 0.f);
                }
            }
            float* EBc = (c & 1) ? EB1 : EB0;
#pragma unroll
            for (int s = 0; s < 4; s++) {
                const int dcol = c * 32 + s * 8 + lr;
                uint32_t A[4][4], B[2][2];
#pragma unroll
                for (int mt = 0; mt < 4; mt++) {
                    A[mt][0] = __float_as_uint(QWK[(mt * 16 + lq) * QWK_S + dcol]);
                    A[mt][1] = __float_as_uint(QWK[(mt * 16 + 8 + lq) * QWK_S + dcol]);
                    A[mt][2] = __float_as_uint(QWK[(mt * 16 + lq) * QWK_S + dcol + 4]);
                    A[mt][3] = __float_as_uint(QWK[(mt * 16 + 8 + lq) * QWK_S + dcol + 4]);
                }
#pragma unroll
                for (int nt = 0; nt < 2; nt++) {
                    int ncol = w * 16 + nt * 8 + lq;
                    B[nt][0] = __float_as_uint(EBc[(s * 8 + lr) * EB_S + ncol]);
                    B[nt][1] = __float_as_uint(EBc[(s * 8 + 4 + lr) * EB_S + ncol]);
                }
#pragma unroll
                for (int mt = 0; mt < 4; mt++)
#pragma unroll
                    for (int nt = 0; nt < 2; nt++) mma8(acc[mt][nt], A[mt], B[nt]);
            }
            __syncthreads();
            if (c < 15) {
                float* EBn = (c & 1) ? EB0 : EB1;
#pragma unroll
                for (int j = 0; j < 4; j++) {
                    int idx = t + j * 256, n = idx & 127, qd = idx >> 7;
                    EBn[(qd * 4 + 0) * EB_S + n] = rr[j].x;
                    EBn[(qd * 4 + 1) * EB_S + n] = rr[j].y;
                    EBn[(qd * 4 + 2) * EB_S + n] = rr[j].z;
                    EBn[(qd * 4 + 3) * EB_S + n] = rr[j].w;
                }
                __syncthreads();
            }
        }
        // epilogue: acc -> CBUF[n][68]
#pragma unroll
        for (int mt = 0; mt < 4; mt++)
#pragma unroll
            for (int nt = 0; nt < 2; nt++) {
                int nb = w * 16 + nt * 8 + 2 * lr;
                int kb = mt * 16 + lq;
                CBUF[nb * 68 + kb]           = acc[mt][nt][0];
                CBUF[(nb + 1) * 68 + kb]     = acc[mt][nt][1];
                CBUF[nb * 68 + kb + 8]       = acc[mt][nt][2];
                CBUF[(nb + 1) * 68 + kb + 8] = acc[mt][nt][3];
            }
        __syncthreads();
        {
            const int n = t >> 1, half = t & 1;
            const int gn = n0 + n;
            if (gn < NN) {
                float* dst = g_P + (size_t)gn * 64 + half * 32;
#pragma unroll
                for (int i = 0; i < 8; i++) {
                    float4 v = *(float4*)(CBUF + n * 68 + half * 32 + i * 4);
                    float4 p;
                    p.x = __expf(v.x * SCALE + sbk[half * 32 + i * 4 + 0]);
                    p.y = __expf(v.y * SCALE + sbk[half * 32 + i * 4 + 1]);
                    p.z = __expf(v.z * SCALE + sbk[half * 32 + i * 4 + 2]);
                    p.w = __expf(v.w * SCALE + sbk[half * 32 + i * 4 + 3]);
                    *(float4*)(dst + i * 4) = p;
                }
            }
        }
        __syncthreads();
    }
}

// ---- K1b: per-head sums of P ----
__global__ __launch_bounds__(256) void sum_kernel() {
    const int k = threadIdx.x & 63, nq = threadIdx.x >> 6;
    const int nb = blockIdx.x * 1000;
    __shared__ float red[256];
    float s = 0.f;
    for (int n = nb + nq; n < nb + 1000 && n < NN; n += 4) s += g_P[(size_t)n * 64 + k];
    red[threadIdx.x] = s;
    __syncthreads();
    if (nq == 0)
        g_sumpart[blockIdx.x * 64 + k] = red[k] + red[64 + k] + red[128 + k] + red[192 + k];
}

// ---- K2: pool partials (f32x2) ----
__global__ __launch_bounds__(256, 2) void pool_kernel(const float* __restrict__ e) {
    __shared__ float Ps[32 * 64];
    __shared__ float Es[32 * 128];
    const int t = threadIdx.x, tx = t & 31, ty = t >> 5;
    const int d0 = (blockIdx.x & 3) * 128;
    const int nbeg = (blockIdx.x >> 2) * SLICE;
    const int nend = (nbeg + SLICE < NN) ? nbeg + SLICE : NN;
    unsigned long long acc[8][2];
#pragma unroll
    for (int a = 0; a < 8; a++) { acc[a][0] = 0ull; acc[a][1] = 0ull; }
    for (int n0 = nbeg; n0 < nend; n0 += 32) {
        __syncthreads();
#pragma unroll
        for (int j = 0; j < 2; j++) {
            int f = t + j * 256, nn = f >> 4, kq = f & 15, n = n0 + nn;
            float4 v = make_float4(0.f, 0.f, 0.f, 0.f);
            if (n < NN) v = *(const float4*)(g_P + (size_t)n * 64 + kq * 4);
            *(float4*)(Ps + nn * 64 + kq * 4) = v;
        }
#pragma unroll
        for (int j = 0; j < 4; j++) {
            int f = t + j * 256, nn = f >> 5, dq = f & 31, n = n0 + nn;
            float4 v = make_float4(0.f, 0.f, 0.f, 0.f);
            if (n < NN) v = *(const float4*)(e + (size_t)n * DD + d0 + dq * 4);
            *(float4*)(Es + nn * 128 + dq * 4) = v;
        }
        __syncthreads();
#pragma unroll
        for (int nn = 0; nn < 32; nn++) {
            float4 a0 = *(const float4*)(Ps + nn * 64 + ty * 8);
            float4 a1 = *(const float4*)(Ps + nn * 64 + ty * 8 + 4);
            float4 bv = *(const float4*)(Es + nn * 128 + tx * 4);
            unsigned long long bp0 = pk2(bv.x, bv.y), bp1 = pk2(bv.z, bv.w);
            float av[8] = {a0.x, a0.y, a0.z, a0.w, a1.x, a1.y, a1.z, a1.w};
#pragma unroll
            for (int kk = 0; kk < 8; kk++) {
                unsigned long long ap = pk2(av[kk], av[kk]);
                fma2(acc[kk][0], ap, bp0);
                fma2(acc[kk][1], ap, bp1);
            }
        }
    }
    float* dst = g_part + (size_t)blockIdx.x * (64 * 128);
#pragma unroll
    for (int kk = 0; kk < 8; kk++) {
        float2 v0 = upk2(acc[kk][0]), v1 = upk2(acc[kk][1]);
        *(float4*)(dst + (ty * 8 + kk) * 128 + tx * 4) = make_float4(v0.x, v0.y, v1.x, v1.y);
    }
}

// ---- K3: reduce ----
__global__ __launch_bounds__(512) void pool_reduce_kernel() {
    const int k = blockIdx.x, d = threadIdx.x, dq = d >> 7, dd = d & 127;
    float s = 0.f;
    for (int bs = 0; bs < NSLICE; bs++)
        s += g_part[(size_t)(bs * 4 + dq) * (64 * 128) + k * 128 + dd];
    g_pooled[k * DD + d] = s;
}

// ---- K4: final ----
__global__ __launch_bounds__(256) void final_kernel(const float* __restrict__ Wv,
        const float* __restrict__ bv, const float* __restrict__ mu_w,
        const float* __restrict__ mu_b, const float* __restrict__ sigma_w,
        const float* __restrict__ sigma_b, float* __restrict__ out) {
    const int k = blockIdx.x, t = threadIdx.x;
    __shared__ float red[256]; __shared__ float ps[DD];
    float s = 0.f;
    for (int b = t; b < SGRID; b += 256) s += g_sumpart[b * 64 + k];
    red[t] = s;
    __syncthreads();
    for (int o = 128; o > 0; o >>= 1) { if (t < o) red[t] += red[t + o]; __syncthreads(); }
    float inv = 1.f / red[0];
    for (int d = t; d < DD; d += 256) ps[d] = g_pooled[k * DD + d] * inv;
    __syncthreads();
    const float* wr = Wv + (size_t)k * HH * DD + (size_t)t * DD;
    float acc = 0.f;
    for (int d = 0; d < DD; d += 4) {
        float4 wv = *(const float4*)(wr + d);
        acc += ps[d] * wv.x + ps[d+1] * wv.y + ps[d+2] * wv.z + ps[d+3] * wv.w;
    }
    float h = acc + bv[k * HH + t];
    float m = h * mu_w[t], g = h * sigma_w[t];
    __syncthreads();
    red[t] = m; __syncthreads();
    for (int o = 128; o > 0; o >>= 1) { if (t < o) red[t] += red[t + o]; __syncthreads(); }
    float mu = red[0] + mu_b[0];
    __syncthreads();
    red[t] = g; __syncthreads();
    for (int o = 128; o > 0; o >>= 1) { if (t < o) red[t] += red[t + o]; __syncthreads(); }
    if (t == 0) { out[k] = mu; out[KK + k] = expf(red[0] + sigma_b[0]); }
}

extern "C" void kernel_launch(void* const* d_in, const int* in_sizes, int n_in,
                              void* d_out, int out_size) {
    const float* e       = (const float*)d_in[0];
    const float* q       = (const float*)d_in[1];
    const float* Wk      = (const float*)d_in[2];
    const float* bk      = (const float*)d_in[3];
    const float* Wv      = (const float*)d_in[4];
    const float* bv      = (const float*)d_in[5];
    const float* mu_w    = (const float*)d_in[6];
    const float* mu_b    = (const float*)d_in[7];
    const float* sigma_w = (const float*)d_in[8];
    const float* sigma_b = (const float*)d_in[9];
    float* out = (float*)d_out;

    cudaFuncSetAttribute(score_kernel, cudaFuncAttributeMaxDynamicSharedMemorySize, SC_SMEM);
    prep_kernel<<<KK, 512>>>(q, Wk, bk);
    score_kernel<<<148, 256, SC_SMEM>>>(e);
    sum_kernel<<<SGRID, 256>>>();
    pool_kernel<<<148, 256>>>(e);
    pool_reduce_kernel<<<KK, 512>>>();
    final_kernel<<<KK, 256>>>(Wv, bv, mu_w, mu_b, sigma_w, sigma_b, out);
}

// round 8
// speedup vs baseline: 1.6496x; 1.5566x over previous
#include <cuda_runtime.h>
#include <math.h>
#include <stdint.h>

// N=200000, D=512, H=256, K=64.
// prep -> score (mma tf32) -> sums -> pool (mma tf32) -> reduce -> final.
#define NN 200000
#define DD 512
#define KK 64
#define HH 256
#define SCALE 0.0625f
#define NTILE 1563
#define SGRID 200
#define PSL_CH 43
#define PSL 1376            // stocks per pool slice (43 chunks of 32)

__device__ __align__(256) float g_qWk[KK * DD];     // [k][d]
__device__ __align__(256) float g_qbk[KK];
__device__ __align__(256) float g_sumpart[SGRID * KK];
__device__ __align__(256) float g_P[(size_t)NN * KK];        // [n][k]
__device__ __align__(256) float g_part2[(size_t)296 * KK * 256];
__device__ __align__(256) float g_pooled[KK * DD];

// ---- tf32 mma (arch-portable HMMA path) ----
__device__ __forceinline__ void mma8(float* c, const uint32_t* a, const uint32_t* b) {
    asm volatile(
        "mma.sync.aligned.m16n8k8.row.col.f32.tf32.tf32.f32 "
        "{%0,%1,%2,%3}, {%4,%5,%6,%7}, {%8,%9}, {%0,%1,%2,%3};"
        : "+f"(c[0]), "+f"(c[1]), "+f"(c[2]), "+f"(c[3])
        : "r"(a[0]), "r"(a[1]), "r"(a[2]), "r"(a[3]), "r"(b[0]), "r"(b[1]));
}
__device__ __forceinline__ void cpa16(uint32_t dst, const void* src) {
    asm volatile("cp.async.cg.shared.global [%0], [%1], 16;" :: "r"(dst), "l"(src));
}
__device__ __forceinline__ uint32_t smem_u32(const void* p) {
    uint32_t a; asm("{ .reg .u64 t; cvta.to.shared.u64 t, %1; cvt.u32.u64 %0, t; }" : "=r"(a) : "l"(p)); return a;
}

// ---- K0: prep ----
__global__ __launch_bounds__(512) void prep_kernel(const float* __restrict__ q,
                                                   const float* __restrict__ Wk,
                                                   const float* __restrict__ bk) {
    const int k = blockIdx.x, t = threadIdx.x;
    __shared__ float qs[HH]; __shared__ float red[256];
    if (t < HH) qs[t] = q[k * HH + t];
    __syncthreads();
    const float* w = Wk + (size_t)k * HH * DD + t;
    float acc = 0.f;
#pragma unroll 8
    for (int h = 0; h < HH; h++) acc += qs[h] * w[(size_t)h * DD];
    g_qWk[k * DD + t] = acc;
    if (t < HH) red[t] = qs[t] * bk[k * HH + t];
    __syncthreads();
    for (int o = 128; o > 0; o >>= 1) { if (t < o) red[t] += red[t + o]; __syncthreads(); }
    if (t == 0) g_qbk[k] = red[0];
}

// ---- K1: score GEMM (mma tf32) + exp (unchanged from R6) ----
#define QWK_S 516
#define EB_S 136
#define EB_OFF 33024
#define SC_SMEM 166912
__global__ __launch_bounds__(256, 1) void score_kernel(const float* __restrict__ e) {
    extern __shared__ float sm[];
    float* QWK = sm;
    float* EB0 = sm + EB_OFF;
    float* EB1 = sm + EB_OFF + 4352;
    float* CBUF = sm + EB_OFF;
    __shared__ float sbk[KK];
    const int t = threadIdx.x, w = t >> 5, lane = t & 31;
    const int lq = lane >> 2, lr = lane & 3;
    if (t < KK) sbk[t] = g_qbk[t] * SCALE;
#pragma unroll
    for (int j = 0; j < 32; j++) {
        int f = t + j * 256, k = f >> 7, c4 = (f & 127) * 4;
        *(float4*)(QWK + k * QWK_S + c4) = *(const float4*)(g_qWk + k * DD + c4);
    }
    __syncthreads();

    for (int tile = blockIdx.x; tile < NTILE; tile += 148) {
        const int n0 = tile * 128;
        float4 rr[4];
#pragma unroll
        for (int j = 0; j < 4; j++) {
            int idx = t + j * 256, n = idx & 127, qd = idx >> 7;
            int gn = n0 + n;
            rr[j] = (gn < NN) ? *(const float4*)(e + (size_t)gn * DD + qd * 4)
                              : make_float4(0.f, 0.f, 0.f, 0.f);
        }
#pragma unroll
        for (int j = 0; j < 4; j++) {
            int idx = t + j * 256, n = idx & 127, qd = idx >> 7;
            EB0[(qd * 4 + 0) * EB_S + n] = rr[j].x;
            EB0[(qd * 4 + 1) * EB_S + n] = rr[j].y;
            EB0[(qd * 4 + 2) * EB_S + n] = rr[j].z;
            EB0[(qd * 4 + 3) * EB_S + n] = rr[j].w;
        }
        __syncthreads();

        float acc[4][2][4];
#pragma unroll
        for (int mt = 0; mt < 4; mt++)
#pragma unroll
            for (int nt = 0; nt < 2; nt++)
#pragma unroll
                for (int i = 0; i < 4; i++) acc[mt][nt][i] = 0.f;

        for (int c = 0; c < 16; c++) {
            if (c < 15) {
#pragma unroll
                for (int j = 0; j < 4; j++) {
                    int idx = t + j * 256, n = idx & 127, qd = idx >> 7;
                    int gn = n0 + n;
                    rr[j] = (gn < NN)
                        ? *(const float4*)(e + (size_t)gn * DD + (c + 1) * 32 + qd * 4)
                        : make_float4(0.f, 0.f, 0.f, 0.f);
                }
            }
            float* EBc = (c & 1) ? EB1 : EB0;
#pragma unroll
            for (int s = 0; s < 4; s++) {
                const int dcol = c * 32 + s * 8 + lr;
                uint32_t A[4][4], B[2][2];
#pragma unroll
                for (int mt = 0; mt < 4; mt++) {
                    A[mt][0] = __float_as_uint(QWK[(mt * 16 + lq) * QWK_S + dcol]);
                    A[mt][1] = __float_as_uint(QWK[(mt * 16 + 8 + lq) * QWK_S + dcol]);
                    A[mt][2] = __float_as_uint(QWK[(mt * 16 + lq) * QWK_S + dcol + 4]);
                    A[mt][3] = __float_as_uint(QWK[(mt * 16 + 8 + lq) * QWK_S + dcol + 4]);
                }
#pragma unroll
                for (int nt = 0; nt < 2; nt++) {
                    int ncol = w * 16 + nt * 8 + lq;
                    B[nt][0] = __float_as_uint(EBc[(s * 8 + lr) * EB_S + ncol]);
                    B[nt][1] = __float_as_uint(EBc[(s * 8 + 4 + lr) * EB_S + ncol]);
                }
#pragma unroll
                for (int mt = 0; mt < 4; mt++)
#pragma unroll
                    for (int nt = 0; nt < 2; nt++) mma8(acc[mt][nt], A[mt], B[nt]);
            }
            __syncthreads();
            if (c < 15) {
                float* EBn = (c & 1) ? EB0 : EB1;
#pragma unroll
                for (int j = 0; j < 4; j++) {
                    int idx = t + j * 256, n = idx & 127, qd = idx >> 7;
                    EBn[(qd * 4 + 0) * EB_S + n] = rr[j].x;
                    EBn[(qd * 4 + 1) * EB_S + n] = rr[j].y;
                    EBn[(qd * 4 + 2) * EB_S + n] = rr[j].z;
                    EBn[(qd * 4 + 3) * EB_S + n] = rr[j].w;
                }
                __syncthreads();
            }
        }
#pragma unroll
        for (int mt = 0; mt < 4; mt++)
#pragma unroll
            for (int nt = 0; nt < 2; nt++) {
                int nb = w * 16 + nt * 8 + 2 * lr;
                int kb = mt * 16 + lq;
                CBUF[nb * 68 + kb]           = acc[mt][nt][0];
                CBUF[(nb + 1) * 68 + kb]     = acc[mt][nt][1];
                CBUF[nb * 68 + kb + 8]       = acc[mt][nt][2];
                CBUF[(nb + 1) * 68 + kb + 8] = acc[mt][nt][3];
            }
        __syncthreads();
        {
            const int n = t >> 1, half = t & 1;
            const int gn = n0 + n;
            if (gn < NN) {
                float* dst = g_P + (size_t)gn * 64 + half * 32;
#pragma unroll
                for (int i = 0; i < 8; i++) {
                    float4 v = *(float4*)(CBUF + n * 68 + half * 32 + i * 4);
                    float4 p;
                    p.x = __expf(v.x * SCALE + sbk[half * 32 + i * 4 + 0]);
                    p.y = __expf(v.y * SCALE + sbk[half * 32 + i * 4 + 1]);
                    p.z = __expf(v.z * SCALE + sbk[half * 32 + i * 4 + 2]);
                    p.w = __expf(v.w * SCALE + sbk[half * 32 + i * 4 + 3]);
                    *(float4*)(dst + i * 4) = p;
                }
            }
        }
        __syncthreads();
    }
}

// ---- K1b: per-head sums of P ----
__global__ __launch_bounds__(256) void sum_kernel() {
    const int k = threadIdx.x & 63, nq = threadIdx.x >> 6;
    const int nb = blockIdx.x * 1000;
    __shared__ float red[256];
    float s = 0.f;
    for (int n = nb + nq; n < nb + 1000 && n < NN; n += 4) s += g_P[(size_t)n * 64 + k];
    red[threadIdx.x] = s;
    __syncthreads();
    if (nq == 0)
        g_sumpart[blockIdx.x * 64 + k] = red[k] + red[64 + k] + red[128 + k] + red[192 + k];
}

// ---- K2: pool GEMM via mma tf32 ----
// C[64 heads x 256 d] per CTA; grid = 148 slices x 2 d-halves.
// smem floats: Ps0 [32][72]=2304 | Ps1 | Es0 [32][264]=8448 | Es1 -> 21504 fl = 86016 B
#define PM_SMEM 86016
__global__ __launch_bounds__(256) void poolmma_kernel(const float* __restrict__ e) {
    extern __shared__ float sm2[];
    float* PsB[2] = {sm2, sm2 + 2304};
    float* EsB[2] = {sm2 + 4608, sm2 + 13056};
    const uint32_t sbase = smem_u32(sm2);
    const int t = threadIdx.x, w = t >> 5, lane = t & 31;
    const int lq = lane >> 2, lr = lane & 3;
    const int dhalf = blockIdx.x & 1, slice = blockIdx.x >> 1;
    const int nbeg = slice * PSL;
    int nch = 0;
    if (nbeg < NN) { int r = (NN - nbeg + 31) / 32; nch = r < PSL_CH ? r : PSL_CH; }

    float acc[4][4][4];
#pragma unroll
    for (int mt = 0; mt < 4; mt++)
#pragma unroll
        for (int nt = 0; nt < 4; nt++)
#pragma unroll
            for (int i = 0; i < 4; i++) acc[mt][nt][i] = 0.f;

    if (nch > 0) {
        // stage chunk 0 into buffer 0
#pragma unroll
        for (int j = 0; j < 8; j++) {          // Es: 32 rows x 64 float4
            int idx = t + j * 256, row = idx >> 6, c4 = idx & 63;
            int gn = nbeg + row;
            uint32_t dst = sbase + (13056 * 0 + 4608 + row * 264 + c4 * 4) * 4
                         - 4608 * 4 + (4608 + row * 264 + c4 * 4) * 0;  // (computed below)
            dst = sbase + (4608 + row * 264 + c4 * 4) * 4;
            if (gn < NN) cpa16(dst, e + (size_t)gn * DD + dhalf * 256 + c4 * 4);
            else *(float4*)(EsB[0] + row * 264 + c4 * 4) = make_float4(0.f, 0.f, 0.f, 0.f);
        }
#pragma unroll
        for (int j = 0; j < 2; j++) {          // Ps: 32 rows x 16 float4
            int idx = t + j * 256, row = idx >> 4, c4 = idx & 15;
            int gn = nbeg + row;
            uint32_t dst = sbase + (row * 72 + c4 * 4) * 4;
            if (gn < NN) cpa16(dst, g_P + (size_t)gn * 64 + c4 * 4);
            else *(float4*)(PsB[0] + row * 72 + c4 * 4) = make_float4(0.f, 0.f, 0.f, 0.f);
        }
        asm volatile("cp.async.commit_group;" ::: "memory");

        for (int c = 0; c < nch; c++) {
            const int b = c & 1;
            if (c + 1 < nch) {
                const int nb2 = (c + 1) & 1;
                const int n1 = nbeg + (c + 1) * 32;
#pragma unroll
                for (int j = 0; j < 8; j++) {
                    int idx = t + j * 256, row = idx >> 6, c4 = idx & 63;
                    int gn = n1 + row;
                    uint32_t dst = sbase + ((4608 + nb2 * 8448) + row * 264 + c4 * 4) * 4;
                    if (gn < NN) cpa16(dst, e + (size_t)gn * DD + dhalf * 256 + c4 * 4);
                    else *(float4*)(EsB[nb2] + row * 264 + c4 * 4) = make_float4(0.f, 0.f, 0.f, 0.f);
                }
#pragma unroll
                for (int j = 0; j < 2; j++) {
                    int idx = t + j * 256, row = idx >> 4, c4 = idx & 15;
                    int gn = n1 + row;
                    uint32_t dst = sbase + ((nb2 * 2304) + row * 72 + c4 * 4) * 4;
                    if (gn < NN) cpa16(dst, g_P + (size_t)gn * 64 + c4 * 4);
                    else *(float4*)(PsB[nb2] + row * 72 + c4 * 4) = make_float4(0.f, 0.f, 0.f, 0.f);
                }
                asm volatile("cp.async.commit_group;" ::: "memory");
                asm volatile("cp.async.wait_group 1;" ::: "memory");
            } else {
                asm volatile("cp.async.wait_group 0;" ::: "memory");
            }
            __syncthreads();
            const float* Ps = PsB[b];
            const float* Es = EsB[b];
#pragma unroll
            for (int s = 0; s < 4; s++) {
                uint32_t A[4][4], B[4][2];
#pragma unroll
                for (int mt = 0; mt < 4; mt++) {
                    A[mt][0] = __float_as_uint(Ps[(s * 8 + lr) * 72 + mt * 16 + lq]);
                    A[mt][1] = __float_as_uint(Ps[(s * 8 + lr) * 72 + mt * 16 + 8 + lq]);
                    A[mt][2] = __float_as_uint(Ps[(s * 8 + 4 + lr) * 72 + mt * 16 + lq]);
                    A[mt][3] = __float_as_uint(Ps[(s * 8 + 4 + lr) * 72 + mt * 16 + 8 + lq]);
                }
#pragma unroll
                for (int nt = 0; nt < 4; nt++) {
                    int dcol = w * 32 + nt * 8 + lq;
                    B[nt][0] = __float_as_uint(Es[(s * 8 + lr) * 264 + dcol]);
                    B[nt][1] = __float_as_uint(Es[(s * 8 + 4 + lr) * 264 + dcol]);
                }
#pragma unroll
                for (int mt = 0; mt < 4; mt++)
#pragma unroll
                    for (int nt = 0; nt < 4; nt++) mma8(acc[mt][nt], A[mt], B[nt]);
            }
            __syncthreads();
        }
    }
    // epilogue: partials [64][256] per CTA
    float* dst = g_part2 + (size_t)blockIdx.x * (64 * 256);
#pragma unroll
    for (int mt = 0; mt < 4; mt++)
#pragma unroll
        for (int nt = 0; nt < 4; nt++) {
            int head = mt * 16 + lq, d = w * 32 + nt * 8 + 2 * lr;
            *(float2*)(dst + head * 256 + d)       = make_float2(acc[mt][nt][0], acc[mt][nt][1]);
            *(float2*)(dst + (head + 8) * 256 + d) = make_float2(acc[mt][nt][2], acc[mt][nt][3]);
        }
}

// ---- K3: reduce 148 slices (fixed order) ----
__global__ __launch_bounds__(512) void pool_reduce_kernel() {
    const int k = blockIdx.x, d = threadIdx.x;
    const int dhalf = d >> 8, dl = d & 255;
    float s = 0.f;
    for (int sl = 0; sl < 148; sl++)
        s += g_part2[(size_t)(sl * 2 + dhalf) * (64 * 256) + k * 256 + dl];
    g_pooled[k * DD + d] = s;
}

// ---- K4: final ----
__global__ __launch_bounds__(256) void final_kernel(const float* __restrict__ Wv,
        const float* __restrict__ bv, const float* __restrict__ mu_w,
        const float* __restrict__ mu_b, const float* __restrict__ sigma_w,
        const float* __restrict__ sigma_b, float* __restrict__ out) {
    const int k = blockIdx.x, t = threadIdx.x;
    __shared__ float red[256]; __shared__ float ps[DD];
    float s = 0.f;
    for (int b = t; b < SGRID; b += 256) s += g_sumpart[b * 64 + k];
    red[t] = s;
    __syncthreads();
    for (int o = 128; o > 0; o >>= 1) { if (t < o) red[t] += red[t + o]; __syncthreads(); }
    float inv = 1.f / red[0];
    for (int d = t; d < DD; d += 256) ps[d] = g_pooled[k * DD + d] * inv;
    __syncthreads();
    const float* wr = Wv + (size_t)k * HH * DD + (size_t)t * DD;
    float acc = 0.f;
    for (int d = 0; d < DD; d += 4) {
        float4 wv = *(const float4*)(wr + d);
        acc += ps[d] * wv.x + ps[d+1] * wv.y + ps[d+2] * wv.z + ps[d+3] * wv.w;
    }
    float h = acc + bv[k * HH + t];
    float m = h * mu_w[t], g = h * sigma_w[t];
    __syncthreads();
    red[t] = m; __syncthreads();
    for (int o = 128; o > 0; o >>= 1) { if (t < o) red[t] += red[t + o]; __syncthreads(); }
    float mu = red[0] + mu_b[0];
    __syncthreads();
    red[t] = g; __syncthreads();
    for (int o = 128; o > 0; o >>= 1) { if (t < o) red[t] += red[t + o]; __syncthreads(); }
    if (t == 0) { out[k] = mu; out[KK + k] = expf(red[0] + sigma_b[0]); }
}

extern "C" void kernel_launch(void* const* d_in, const int* in_sizes, int n_in,
                              void* d_out, int out_size) {
    const float* e       = (const float*)d_in[0];
    const float* q       = (const float*)d_in[1];
    const float* Wk      = (const float*)d_in[2];
    const float* bk      = (const float*)d_in[3];
    const float* Wv      = (const float*)d_in[4];
    const float* bv      = (const float*)d_in[5];
    const float* mu_w    = (const float*)d_in[6];
    const float* mu_b    = (const float*)d_in[7];
    const float* sigma_w = (const float*)d_in[8];
    const float* sigma_b = (const float*)d_in[9];
    float* out = (float*)d_out;

    cudaFuncSetAttribute(score_kernel, cudaFuncAttributeMaxDynamicSharedMemorySize, SC_SMEM);
    cudaFuncSetAttribute(poolmma_kernel, cudaFuncAttributeMaxDynamicSharedMemorySize, PM_SMEM);
    prep_kernel<<<KK, 512>>>(q, Wk, bk);
    score_kernel<<<148, 256, SC_SMEM>>>(e);
    sum_kernel<<<SGRID, 256>>>();
    poolmma_kernel<<<296, 256, PM_SMEM>>>(e);
    pool_reduce_kernel<<<KK, 512>>>();
    final_kernel<<<KK, 256>>>(Wv, bv, mu_w, mu_b, sigma_w, sigma_b, out);
}

// round 9
// speedup vs baseline: 2.5541x; 1.5483x over previous
#include <cuda_runtime.h>
#include <math.h>
#include <stdint.h>

// N=200000, D=512, H=256, K=64.
// prep -> score (mma tf32, fused sums) -> pool (mma tf32) -> reduce -> final.
#define NN 200000
#define DD 512
#define KK 64
#define HH 256
#define SCALE 0.0625f
#define NT2 782             // ceil(200000/256) score tiles
#define SGRID 148
#define PSL_CH 43
#define PSL 1376

__device__ __align__(256) float g_qWk[KK * DD];     // [k][d]
__device__ __align__(256) float g_qbk[KK];
__device__ __align__(256) float g_sumpart[SGRID * KK];
__device__ __align__(256) float g_P[(size_t)NN * KK];        // [n][k]
__device__ __align__(256) float g_part2[(size_t)296 * KK * 256];
__device__ __align__(256) float g_pooled[KK * DD];

__device__ __forceinline__ void mma8(float* c, const uint32_t* a, const uint32_t* b) {
    asm volatile(
        "mma.sync.aligned.m16n8k8.row.col.f32.tf32.tf32.f32 "
        "{%0,%1,%2,%3}, {%4,%5,%6,%7}, {%8,%9}, {%0,%1,%2,%3};"
        : "+f"(c[0]), "+f"(c[1]), "+f"(c[2]), "+f"(c[3])
        : "r"(a[0]), "r"(a[1]), "r"(a[2]), "r"(a[3]), "r"(b[0]), "r"(b[1]));
}
__device__ __forceinline__ void cpa16(uint32_t dst, const void* src) {
    asm volatile("cp.async.cg.shared.global [%0], [%1], 16;" :: "r"(dst), "l"(src));
}
__device__ __forceinline__ uint32_t smem_u32(const void* p) {
    uint32_t a; asm("{ .reg .u64 t; cvta.to.shared.u64 t, %1; cvt.u32.u64 %0, t; }" : "=r"(a) : "l"(p)); return a;
}

// ---- K0: prep ----
__global__ __launch_bounds__(512) void prep_kernel(const float* __restrict__ q,
                                                   const float* __restrict__ Wk,
                                                   const float* __restrict__ bk) {
    const int k = blockIdx.x, t = threadIdx.x;
    __shared__ float qs[HH]; __shared__ float red[256];
    if (t < HH) qs[t] = q[k * HH + t];
    __syncthreads();
    const float* w = Wk + (size_t)k * HH * DD + t;
    float acc = 0.f;
#pragma unroll 8
    for (int h = 0; h < HH; h++) acc += qs[h] * w[(size_t)h * DD];
    g_qWk[k * DD + t] = acc;
    if (t < HH) red[t] = qs[t] * bk[k * HH + t];
    __syncthreads();
    for (int o = 128; o > 0; o >>= 1) { if (t < o) red[t] += red[t + o]; __syncthreads(); }
    if (t == 0) g_qbk[k] = red[0];
}

// ---- K1: score GEMM + exp + fused per-head sums ----
// dyn smem floats: QWK [64][516]=33024 | Es x2 [256][36]=9216 each -> 51456 fl = 205824 B
#define QWK_S 516
#define ES_S 36
#define ES_OFF 33024
#define ES_BUF 9216
#define SC_SMEM 205824
__global__ __launch_bounds__(512, 1) void score_kernel(const float* __restrict__ e) {
    extern __shared__ float sm[];
    float* QWK = sm;
    const uint32_t sbase = smem_u32(sm);
    __shared__ float sbk[KK];
    __shared__ float sums[16][KK];
    const int t = threadIdx.x, w = t >> 5, lane = t & 31;
    const int lq = lane >> 2, lr = lane & 3;
    if (t < KK) sbk[t] = g_qbk[t] * SCALE;
#pragma unroll
    for (int j = 0; j < 16; j++) {
        int idx = t + j * 512, k = idx >> 7, c4 = (idx & 127) * 4;
        *(float4*)(QWK + k * QWK_S + c4) = *(const float4*)(g_qWk + k * DD + c4);
    }
    __syncthreads();

    float sumacc[8][2];
#pragma unroll
    for (int nt = 0; nt < 8; nt++) { sumacc[nt][0] = 0.f; sumacc[nt][1] = 0.f; }

    for (int tile = blockIdx.x; tile < NT2; tile += 148) {
        const int n0 = tile * 256;
        // stage chunk 0 -> buf 0
#pragma unroll
        for (int j = 0; j < 4; j++) {
            int idx = t + j * 512, row = idx >> 3, qd = idx & 7;
            int gn = n0 + row, off = ES_OFF + row * ES_S + qd * 4;
            if (gn < NN) cpa16(sbase + off * 4, e + (size_t)gn * DD + qd * 4);
            else *(float4*)(sm + off) = make_float4(0.f, 0.f, 0.f, 0.f);
        }
        asm volatile("cp.async.commit_group;" ::: "memory");

        float acc[8][4];
#pragma unroll
        for (int nt = 0; nt < 8; nt++)
#pragma unroll
            for (int i = 0; i < 4; i++) acc[nt][i] = 0.f;

        for (int c = 0; c < 16; c++) {
            if (c < 15) {
                const int bn = (c + 1) & 1;
#pragma unroll
                for (int j = 0; j < 4; j++) {
                    int idx = t + j * 512, row = idx >> 3, qd = idx & 7;
                    int gn = n0 + row, off = ES_OFF + bn * ES_BUF + row * ES_S + qd * 4;
                    if (gn < NN) cpa16(sbase + off * 4, e + (size_t)gn * DD + (c + 1) * 32 + qd * 4);
                    else *(float4*)(sm + off) = make_float4(0.f, 0.f, 0.f, 0.f);
                }
                asm volatile("cp.async.commit_group;" ::: "memory");
                asm volatile("cp.async.wait_group 1;" ::: "memory");
            } else {
                asm volatile("cp.async.wait_group 0;" ::: "memory");
            }
            __syncthreads();
            const float* Es = sm + ES_OFF + (c & 1) * ES_BUF;
#pragma unroll
            for (int s = 0; s < 4; s++) {
                uint32_t A[4], B[8][2];
                const int ar = (w * 16 + lq) * ES_S + s * 8 + lr;
                A[0] = __float_as_uint(Es[ar]);
                A[1] = __float_as_uint(Es[ar + 8 * ES_S]);
                A[2] = __float_as_uint(Es[ar + 4]);
                A[3] = __float_as_uint(Es[ar + 8 * ES_S + 4]);
                const int bcol = c * 32 + s * 8 + lr;
#pragma unroll
                for (int nt = 0; nt < 8; nt++) {
                    B[nt][0] = __float_as_uint(QWK[(nt * 8 + lq) * QWK_S + bcol]);
                    B[nt][1] = __float_as_uint(QWK[(nt * 8 + lq) * QWK_S + bcol + 4]);
                }
#pragma unroll
                for (int nt = 0; nt < 8; nt++) mma8(acc[nt], A, B[nt]);
            }
            __syncthreads();
        }
        // epilogue: exp + store P + accumulate head sums
        const int r0 = n0 + w * 16 + lq, r1 = r0 + 8;
        const bool ok0 = r0 < NN, ok1 = r1 < NN;
#pragma unroll
        for (int nt = 0; nt < 8; nt++) {
            const int h = nt * 8 + 2 * lr;
            const float b0 = sbk[h], b1 = sbk[h + 1];
            if (ok0) {
                float p0 = __expf(acc[nt][0] * SCALE + b0);
                float p1 = __expf(acc[nt][1] * SCALE + b1);
                *(float2*)(g_P + (size_t)r0 * 64 + h) = make_float2(p0, p1);
                sumacc[nt][0] += p0; sumacc[nt][1] += p1;
            }
            if (ok1) {
                float p0 = __expf(acc[nt][2] * SCALE + b0);
                float p1 = __expf(acc[nt][3] * SCALE + b1);
                *(float2*)(g_P + (size_t)r1 * 64 + h) = make_float2(p0, p1);
                sumacc[nt][0] += p0; sumacc[nt][1] += p1;
            }
        }
    }
    // reduce sums: lanes differing only in lq share the same head columns
#pragma unroll
    for (int off = 4; off <= 16; off <<= 1)
#pragma unroll
        for (int nt = 0; nt < 8; nt++) {
            sumacc[nt][0] += __shfl_xor_sync(0xffffffffu, sumacc[nt][0], off);
            sumacc[nt][1] += __shfl_xor_sync(0xffffffffu, sumacc[nt][1], off);
        }
    if (lane < 4)
#pragma unroll
        for (int nt = 0; nt < 8; nt++) {
            sums[w][nt * 8 + 2 * lane] = sumacc[nt][0];
            sums[w][nt * 8 + 2 * lane + 1] = sumacc[nt][1];
        }
    __syncthreads();
    if (t < KK) {
        float s = 0.f;
#pragma unroll
        for (int ww = 0; ww < 16; ww++) s += sums[ww][t];
        g_sumpart[blockIdx.x * 64 + t] = s;
    }
}

// ---- K2: pool GEMM via mma tf32 (unchanged from R7) ----
#define PM_SMEM 86016
__global__ __launch_bounds__(256) void poolmma_kernel(const float* __restrict__ e) {
    extern __shared__ float sm2[];
    float* PsB[2] = {sm2, sm2 + 2304};
    float* EsB[2] = {sm2 + 4608, sm2 + 13056};
    const uint32_t sbase = smem_u32(sm2);
    const int t = threadIdx.x, w = t >> 5, lane = t & 31;
    const int lq = lane >> 2, lr = lane & 3;
    const int dhalf = blockIdx.x & 1, slice = blockIdx.x >> 1;
    const int nbeg = slice * PSL;
    int nch = 0;
    if (nbeg < NN) { int r = (NN - nbeg + 31) / 32; nch = r < PSL_CH ? r : PSL_CH; }

    float acc[4][4][4];
#pragma unroll
    for (int mt = 0; mt < 4; mt++)
#pragma unroll
        for (int nt = 0; nt < 4; nt++)
#pragma unroll
            for (int i = 0; i < 4; i++) acc[mt][nt][i] = 0.f;

    if (nch > 0) {
#pragma unroll
        for (int j = 0; j < 8; j++) {
            int idx = t + j * 256, row = idx >> 6, c4 = idx & 63;
            int gn = nbeg + row;
            uint32_t dst = sbase + (4608 + row * 264 + c4 * 4) * 4;
            if (gn < NN) cpa16(dst, e + (size_t)gn * DD + dhalf * 256 + c4 * 4);
            else *(float4*)(EsB[0] + row * 264 + c4 * 4) = make_float4(0.f, 0.f, 0.f, 0.f);
        }
#pragma unroll
        for (int j = 0; j < 2; j++) {
            int idx = t + j * 256, row = idx >> 4, c4 = idx & 15;
            int gn = nbeg + row;
            uint32_t dst = sbase + (row * 72 + c4 * 4) * 4;
            if (gn < NN) cpa16(dst, g_P + (size_t)gn * 64 + c4 * 4);
            else *(float4*)(PsB[0] + row * 72 + c4 * 4) = make_float4(0.f, 0.f, 0.f, 0.f);
        }
        asm volatile("cp.async.commit_group;" ::: "memory");

        for (int c = 0; c < nch; c++) {
            const int b = c & 1;
            if (c + 1 < nch) {
                const int nb2 = (c + 1) & 1;
                const int n1 = nbeg + (c + 1) * 32;
#pragma unroll
                for (int j = 0; j < 8; j++) {
                    int idx = t + j * 256, row = idx >> 6, c4 = idx & 63;
                    int gn = n1 + row;
                    uint32_t dst = sbase + ((4608 + nb2 * 8448) + row * 264 + c4 * 4) * 4;
                    if (gn < NN) cpa16(dst, e + (size_t)gn * DD + dhalf * 256 + c4 * 4);
                    else *(float4*)(EsB[nb2] + row * 264 + c4 * 4) = make_float4(0.f, 0.f, 0.f, 0.f);
                }
#pragma unroll
                for (int j = 0; j < 2; j++) {
                    int idx = t + j * 256, row = idx >> 4, c4 = idx & 15;
                    int gn = n1 + row;
                    uint32_t dst = sbase + ((nb2 * 2304) + row * 72 + c4 * 4) * 4;
                    if (gn < NN) cpa16(dst, g_P + (size_t)gn * 64 + c4 * 4);
                    else *(float4*)(PsB[nb2] + row * 72 + c4 * 4) = make_float4(0.f, 0.f, 0.f, 0.f);
                }
                asm volatile("cp.async.commit_group;" ::: "memory");
                asm volatile("cp.async.wait_group 1;" ::: "memory");
            } else {
                asm volatile("cp.async.wait_group 0;" ::: "memory");
            }
            __syncthreads();
            const float* Ps = PsB[b];
            const float* Es = EsB[b];
#pragma unroll
            for (int s = 0; s < 4; s++) {
                uint32_t A[4][4], B[4][2];
#pragma unroll
                for (int mt = 0; mt < 4; mt++) {
                    A[mt][0] = __float_as_uint(Ps[(s * 8 + lr) * 72 + mt * 16 + lq]);
                    A[mt][1] = __float_as_uint(Ps[(s * 8 + lr) * 72 + mt * 16 + 8 + lq]);
                    A[mt][2] = __float_as_uint(Ps[(s * 8 + 4 + lr) * 72 + mt * 16 + lq]);
                    A[mt][3] = __float_as_uint(Ps[(s * 8 + 4 + lr) * 72 + mt * 16 + 8 + lq]);
                }
#pragma unroll
                for (int nt = 0; nt < 4; nt++) {
                    int dcol = w * 32 + nt * 8 + lq;
                    B[nt][0] = __float_as_uint(Es[(s * 8 + lr) * 264 + dcol]);
                    B[nt][1] = __float_as_uint(Es[(s * 8 + 4 + lr) * 264 + dcol]);
                }
#pragma unroll
                for (int mt = 0; mt < 4; mt++)
#pragma unroll
                    for (int nt = 0; nt < 4; nt++) mma8(acc[mt][nt], A[mt], B[nt]);
            }
            __syncthreads();
        }
    }
    float* dst = g_part2 + (size_t)blockIdx.x * (64 * 256);
#pragma unroll
    for (int mt = 0; mt < 4; mt++)
#pragma unroll
        for (int nt = 0; nt < 4; nt++) {
            int head = mt * 16 + lq, d = w * 32 + nt * 8 + 2 * lr;
            *(float2*)(dst + head * 256 + d)       = make_float2(acc[mt][nt][0], acc[mt][nt][1]);
            *(float2*)(dst + (head + 8) * 256 + d) = make_float2(acc[mt][nt][2], acc[mt][nt][3]);
        }
}

// ---- K3: reduce ----
__global__ __launch_bounds__(512) void pool_reduce_kernel() {
    const int k = blockIdx.x, d = threadIdx.x;
    const int dhalf = d >> 8, dl = d & 255;
    float s = 0.f;
    for (int sl = 0; sl < 148; sl++)
        s += g_part2[(size_t)(sl * 2 + dhalf) * (64 * 256) + k * 256 + dl];
    g_pooled[k * DD + d] = s;
}

// ---- K4: final ----
__global__ __launch_bounds__(256) void final_kernel(const float* __restrict__ Wv,
        const float* __restrict__ bv, const float* __restrict__ mu_w,
        const float* __restrict__ mu_b, const float* __restrict__ sigma_w,
        const float* __restrict__ sigma_b, float* __restrict__ out) {
    const int k = blockIdx.x, t = threadIdx.x;
    __shared__ float red[256]; __shared__ float ps[DD];
    float s = 0.f;
    for (int b = t; b < SGRID; b += 256) s += g_sumpart[b * 64 + k];
    red[t] = s;
    __syncthreads();
    for (int o = 128; o > 0; o >>= 1) { if (t < o) red[t] += red[t + o]; __syncthreads(); }
    float inv = 1.f / red[0];
    for (int d = t; d < DD; d += 256) ps[d] = g_pooled[k * DD + d] * inv;
    __syncthreads();
    const float* wr = Wv + (size_t)k * HH * DD + (size_t)t * DD;
    float acc = 0.f;
    for (int d = 0; d < DD; d += 4) {
        float4 wv = *(const float4*)(wr + d);
        acc += ps[d] * wv.x + ps[d+1] * wv.y + ps[d+2] * wv.z + ps[d+3] * wv.w;
    }
    float h = acc + bv[k * HH + t];
    float m = h * mu_w[t], g = h * sigma_w[t];
    __syncthreads();
    red[t] = m; __syncthreads();
    for (int o = 128; o > 0; o >>= 1) { if (t < o) red[t] += red[t + o]; __syncthreads(); }
    float mu = red[0] + mu_b[0];
    __syncthreads();
    red[t] = g; __syncthreads();
    for (int o = 128; o > 0; o >>= 1) { if (t < o) red[t] += red[t + o]; __syncthreads(); }
    if (t == 0) { out[k] = mu; out[KK + k] = expf(red[0] + sigma_b[0]); }
}

extern "C" void kernel_launch(void* const* d_in, const int* in_sizes, int n_in,
                              void* d_out, int out_size) {
    const float* e       = (const float*)d_in[0];
    const float* q       = (const float*)d_in[1];
    const float* Wk      = (const float*)d_in[2];
    const float* bk      = (const float*)d_in[3];
    const float* Wv      = (const float*)d_in[4];
    const float* bv      = (const float*)d_in[5];
    const float* mu_w    = (const float*)d_in[6];
    const float* mu_b    = (const float*)d_in[7];
    const float* sigma_w = (const float*)d_in[8];
    const float* sigma_b = (const float*)d_in[9];
    float* out = (float*)d_out;

    cudaFuncSetAttribute(score_kernel, cudaFuncAttributeMaxDynamicSharedMemorySize, SC_SMEM);
    cudaFuncSetAttribute(poolmma_kernel, cudaFuncAttributeMaxDynamicSharedMemorySize, PM_SMEM);
    prep_kernel<<<KK, 512>>>(q, Wk, bk);
    score_kernel<<<148, 512, SC_SMEM>>>(e);
    poolmma_kernel<<<296, 256, PM_SMEM>>>(e);
    pool_reduce_kernel<<<KK, 512>>>();
    final_kernel<<<KK, 256>>>(Wv, bv, mu_w, mu_b, sigma_w, sigma_b, out);
}